// round 1
// baseline (speedup 1.0000x reference)
#include <cuda_runtime.h>
#include <cuda_bf16.h>
#include <math.h>

// Problem constants
#define BB 64
#define TT 128
#define TS 127          // timesteps = T-1
#define VV 10000
#define EE 300
#define HH 1024
#define G4 4096         // 4*H

// ---------------- scratch (static device memory; no allocations) -------------
__device__ float g_pre0[(size_t)TS * BB * G4];     // x@w_ih0 + b0, row = t*64+b
__device__ float g_h1all[(size_t)TS * BB * HH];    // all layer-1 hidden states
__device__ float g_h0buf[2][BB * HH];
__device__ float g_c0[BB * HH];
__device__ float g_c1[BB * HH];
__device__ float g_h1zero[BB * HH];
__device__ float g_rowloss[TS * BB];

__device__ __forceinline__ float sigmoidf_(float x) {
    return 1.0f / (1.0f + expf(-x));
}

// ---------------- init: zero recurrent state every replay --------------------
__global__ void init_state_kernel() {
    int i = blockIdx.x * blockDim.x + threadIdx.x;
    if (i < BB * HH) {
        g_h0buf[0][i] = 0.f;
        g_c0[i] = 0.f;
        g_c1[i] = 0.f;
        g_h1zero[i] = 0.f;
    }
}

// ---------------- pre0 = gather(emb) @ w_ih0 + b0 ----------------------------
// M=8128 (row=t*64+b), N=4096, K=300. BM=BN=64, BK=4, 256 thr, 4x4/thread.
__global__ __launch_bounds__(256) void pre0_gemm_kernel(
    const int* __restrict__ sent, const float* __restrict__ wordvec,
    const float* __restrict__ w_ih0, const float* __restrict__ b0)
{
    __shared__ float As[4][64];
    __shared__ float Bs[4][64];
    const int t = blockIdx.y;             // 0..126
    const int colBase = blockIdx.x * 64;  // 0..4032
    const int tid = threadIdx.x;
    const int tx = tid & 15, ty = tid >> 4;

    const float* arow = nullptr;
    if (tid < 64) {
        int token = sent[tid * TT + t];
        arow = wordvec + (size_t)token * EE;
    }
    const int bRow = tid >> 6, bCol = tid & 63;

    float acc[4][4] = {};
    for (int kt = 0; kt < 75; kt++) {
        __syncthreads();
        if (tid < 64) {
            float4 a = *(const float4*)(arow + kt * 4);
            As[0][tid] = a.x; As[1][tid] = a.y; As[2][tid] = a.z; As[3][tid] = a.w;
        }
        Bs[bRow][bCol] = w_ih0[(size_t)(kt * 4 + bRow) * G4 + colBase + bCol];
        __syncthreads();
#pragma unroll
        for (int k = 0; k < 4; k++) {
            float4 a4 = *(const float4*)&As[k][ty * 4];
            float4 b4 = *(const float4*)&Bs[k][tx * 4];
            acc[0][0] += a4.x * b4.x; acc[0][1] += a4.x * b4.y; acc[0][2] += a4.x * b4.z; acc[0][3] += a4.x * b4.w;
            acc[1][0] += a4.y * b4.x; acc[1][1] += a4.y * b4.y; acc[1][2] += a4.y * b4.z; acc[1][3] += a4.y * b4.w;
            acc[2][0] += a4.z * b4.x; acc[2][1] += a4.z * b4.y; acc[2][2] += a4.z * b4.z; acc[2][3] += a4.z * b4.w;
            acc[3][0] += a4.w * b4.x; acc[3][1] += a4.w * b4.y; acc[3][2] += a4.w * b4.z; acc[3][3] += a4.w * b4.w;
        }
    }
    float* dst = g_pre0 + ((size_t)t * 64) * G4 + colBase;
#pragma unroll
    for (int i = 0; i < 4; i++) {
        int b_ = ty * 4 + i;
#pragma unroll
        for (int j = 0; j < 4; j++) {
            int c = tx * 4 + j;
            dst[(size_t)b_ * G4 + c] = acc[i][j] + b0[colBase + c];
        }
    }
}

// ---------------- one LSTM step (one layer) ----------------------------------
// grid 128 (j-tiles of 8), 256 threads: b = tid&63, jq = tid>>6 (2 j each).
// gates[b][g*1024+j] = sum over segments h_seg @ w_seg + addvec
__global__ __launch_bounds__(256) void lstm_step_kernel(
    int layer, int t,
    const float* __restrict__ wA, const float* __restrict__ wB,
    const float* __restrict__ bias1)
{
    __shared__ float hs[64 * 65];
    __shared__ float ws[64 * 32];   // [k][j_in_tile 0..7][g 0..3]

    const int tid = threadIdx.x;
    const int b = tid & 63, jq = tid >> 6;
    const int j0 = blockIdx.x * 8;

    const float* hA; const float* hB = nullptr;
    const float* addvec; int addstride;
    float* cst; float* hout;
    if (layer == 0) {
        hA = g_h0buf[t & 1];
        addvec = g_pre0 + (size_t)t * BB * G4; addstride = G4;
        cst = g_c0; hout = g_h0buf[(t + 1) & 1];
    } else {
        hA = g_h0buf[(t + 1) & 1];
        hB = (t > 0) ? (g_h1all + (size_t)(t - 1) * BB * HH) : g_h1zero;
        addvec = bias1; addstride = 0;
        cst = g_c1; hout = g_h1all + (size_t)t * BB * HH;
    }

    float a00=0,a01=0,a02=0,a03=0,a10=0,a11=0,a12=0,a13=0;
    const float4* ws4 = (const float4*)ws;

    for (int seg = 0; seg < 2; seg++) {
        const float* h = seg ? hB : hA;
        const float* w = seg ? wB : wA;
        if (h == nullptr) break;
        for (int kb = 0; kb < HH; kb += 64) {
            __syncthreads();
            // h tile: hs[k][b], padded stride 65
            for (int i = tid; i < 64 * 64; i += 256) {
                int bb = i >> 6, kk = i & 63;
                hs[kk * 65 + bb] = h[(size_t)bb * HH + kb + kk];
            }
            // w tile: ws[k][jj][g]
            for (int i = tid; i < 64 * 32; i += 256) {
                int kk = i >> 5, r = i & 31;
                int g = r >> 3, jj = r & 7;
                ws[kk * 32 + jj * 4 + g] = w[(size_t)(kb + kk) * G4 + g * HH + j0 + jj];
            }
            __syncthreads();
#pragma unroll 4
            for (int kk = 0; kk < 64; kk++) {
                float hv = hs[kk * 65 + b];
                float4 w0 = ws4[kk * 8 + jq * 2];
                float4 w1 = ws4[kk * 8 + jq * 2 + 1];
                a00 += hv * w0.x; a01 += hv * w0.y; a02 += hv * w0.z; a03 += hv * w0.w;
                a10 += hv * w1.x; a11 += hv * w1.y; a12 += hv * w1.z; a13 += hv * w1.w;
            }
        }
    }

    const float* av = addvec + (size_t)b * addstride;
    {   // jj = 0
        int j = j0 + jq * 2;
        float gi = a00 + av[j];
        float gf = a01 + av[HH + j];
        float gg = a02 + av[2 * HH + j];
        float go = a03 + av[3 * HH + j];
        float c  = cst[(size_t)b * HH + j];
        float cn = sigmoidf_(gf) * c + sigmoidf_(gi) * tanhf(gg);
        float hn = sigmoidf_(go) * tanhf(cn);
        cst[(size_t)b * HH + j]  = cn;
        hout[(size_t)b * HH + j] = hn;
    }
    {   // jj = 1
        int j = j0 + jq * 2 + 1;
        float gi = a10 + av[j];
        float gf = a11 + av[HH + j];
        float gg = a12 + av[2 * HH + j];
        float go = a13 + av[3 * HH + j];
        float c  = cst[(size_t)b * HH + j];
        float cn = sigmoidf_(gf) * c + sigmoidf_(gi) * tanhf(gg);
        float hn = sigmoidf_(go) * tanhf(cn);
        cst[(size_t)b * HH + j]  = cn;
        hout[(size_t)b * HH + j] = hn;
    }
}

// ---------------- logits = h1all @ w_out + b_out -----------------------------
// M=8128, N=10000, K=1024. BM=BN=64, BK=16, 256 thr, 4x4/thread.
// Writes temp[b][t][v] directly.
__global__ __launch_bounds__(256) void logits_gemm_kernel(
    const float* __restrict__ w_out, const float* __restrict__ b_out,
    float* __restrict__ temp)
{
    __shared__ float As[16][64];
    __shared__ float Bs[16][64];
    const int t = blockIdx.y;
    const int colBase = blockIdx.x * 64;
    const int tid = threadIdx.x;
    const int tx = tid & 15, ty = tid >> 4;
    const int aRow = tid >> 2, aK = (tid & 3) * 4;
    const int bRow = tid >> 4, bCol = (tid & 15) * 4;
    const bool fullTile = (colBase + 64 <= VV);

    const float* Aptr = g_h1all + ((size_t)t * 64 + aRow) * HH + aK;

    float acc[4][4] = {};
    for (int kt = 0; kt < 64; kt++) {
        __syncthreads();
        float4 a = *(const float4*)(Aptr + kt * 16);
        As[aK + 0][aRow] = a.x; As[aK + 1][aRow] = a.y;
        As[aK + 2][aRow] = a.z; As[aK + 3][aRow] = a.w;
        int col = colBase + bCol;
        const float* bp = w_out + (size_t)(kt * 16 + bRow) * VV + col;
        if (fullTile || col + 3 < VV) {
            *(float4*)&Bs[bRow][bCol] = *(const float4*)bp;
        } else {
#pragma unroll
            for (int q = 0; q < 4; q++)
                Bs[bRow][bCol + q] = (col + q < VV) ? bp[q] : 0.f;
        }
        __syncthreads();
#pragma unroll
        for (int k = 0; k < 16; k++) {
            float4 a4 = *(const float4*)&As[k][ty * 4];
            float4 b4 = *(const float4*)&Bs[k][tx * 4];
            acc[0][0] += a4.x * b4.x; acc[0][1] += a4.x * b4.y; acc[0][2] += a4.x * b4.z; acc[0][3] += a4.x * b4.w;
            acc[1][0] += a4.y * b4.x; acc[1][1] += a4.y * b4.y; acc[1][2] += a4.y * b4.z; acc[1][3] += a4.y * b4.w;
            acc[2][0] += a4.z * b4.x; acc[2][1] += a4.z * b4.y; acc[2][2] += a4.z * b4.z; acc[2][3] += a4.z * b4.w;
            acc[3][0] += a4.w * b4.x; acc[3][1] += a4.w * b4.y; acc[3][2] += a4.w * b4.z; acc[3][3] += a4.w * b4.w;
        }
    }
#pragma unroll
    for (int i = 0; i < 4; i++) {
        int b_ = ty * 4 + i;
#pragma unroll
        for (int j = 0; j < 4; j++) {
            int col = colBase + tx * 4 + j;
            if (col < VV)
                temp[((size_t)b_ * TS + t) * VV + col] = acc[i][j] + b_out[col];
        }
    }
}

// ---------------- loss: per-row -logp/length (deterministic) -----------------
__global__ __launch_bounds__(256) void loss_row_kernel(
    const float* __restrict__ temp, const int* __restrict__ sent,
    const int* __restrict__ length)
{
    __shared__ float sm[256];
    __shared__ float ss[256];
    const int row = blockIdx.x;            // b*127 + t
    const int b = row / TS, t = row % TS;
    const float* x = temp + (size_t)row * VV;
    const int tid = threadIdx.x;

    float m = -1e30f, s = 0.f;
    for (int i = tid; i < VV; i += 256) {
        float v = x[i];
        float M = fmaxf(m, v);
        s = s * expf(m - M) + expf(v - M);
        m = M;
    }
    sm[tid] = m; ss[tid] = s;
    __syncthreads();
    for (int w = 128; w > 0; w >>= 1) {
        if (tid < w) {
            float m2 = sm[tid + w], s2 = ss[tid + w];
            float M = fmaxf(sm[tid], m2);
            ss[tid] = ss[tid] * expf(sm[tid] - M) + s2 * expf(m2 - M);
            sm[tid] = M;
        }
        __syncthreads();
    }
    if (tid == 0) {
        int gt = sent[b * TT + t + 1];
        float lse = sm[0] + logf(ss[0]);
        float res = 0.f;
        if (gt != 0) {
            float lp = x[gt] - lse;
            res = -lp / (float)length[b];
        }
        g_rowloss[row] = res;
    }
}

__global__ __launch_bounds__(256) void loss_final_kernel(float* __restrict__ out) {
    __shared__ float s[256];
    const int tid = threadIdx.x;
    float a = 0.f;
    for (int i = tid; i < TS * BB; i += 256) a += g_rowloss[i];
    s[tid] = a;
    __syncthreads();
    for (int w = 128; w > 0; w >>= 1) {
        if (tid < w) s[tid] += s[tid + w];
        __syncthreads();
    }
    if (tid == 0) out[0] = s[0];
}

// ---------------- host launcher ----------------------------------------------
extern "C" void kernel_launch(void* const* d_in, const int* in_sizes, int n_in,
                              void* d_out, int out_size)
{
    const int*   sent    = (const int*)d_in[0];
    const int*   length  = (const int*)d_in[1];
    const float* wordvec = (const float*)d_in[2];
    const float* w_ih0   = (const float*)d_in[3];
    const float* w_hh0   = (const float*)d_in[4];
    const float* b0      = (const float*)d_in[5];
    const float* w_ih1   = (const float*)d_in[6];
    const float* w_hh1   = (const float*)d_in[7];
    const float* b1      = (const float*)d_in[8];
    const float* w_out   = (const float*)d_in[9];
    const float* b_out   = (const float*)d_in[10];
    float* out = (float*)d_out;

    const long long TEMP_N = (long long)BB * TS * VV;
    int off = ((long long)out_size > TEMP_N) ? (int)((long long)out_size - TEMP_N) : 0;
    float* temp = out + off;

    init_state_kernel<<<256, 256>>>();
    pre0_gemm_kernel<<<dim3(64, TS), 256>>>(sent, wordvec, w_ih0, b0);
    for (int t = 0; t < TS; t++) {
        lstm_step_kernel<<<128, 256>>>(0, t, w_hh0, nullptr, nullptr);
        lstm_step_kernel<<<128, 256>>>(1, t, w_ih1, w_hh1, b1);
    }
    logits_gemm_kernel<<<dim3(157, TS), 256>>>(w_out, b_out, temp);
    if (off > 0) {
        loss_row_kernel<<<TS * BB, 256>>>(temp, sent, length);
        loss_final_kernel<<<1, 256>>>(out);
    }
}

// round 2
// speedup vs baseline: 1.5029x; 1.5029x over previous
#include <cuda_runtime.h>
#include <cuda_bf16.h>
#include <math.h>

// Problem constants
#define BB 64
#define TT 128
#define TS 127          // timesteps = T-1
#define VV 10000
#define EE 300
#define HH 1024
#define G4 4096         // 4*H

typedef unsigned long long u64;

// ---------------- scratch (static device memory; no allocations) -------------
__device__ float g_pre0[(size_t)TS * BB * G4];     // x@w_ih0 + b0, row = t*64+b
__device__ float g_h1all[(size_t)TS * BB * HH];    // all layer-1 hidden states
__device__ float g_h0buf[2][BB * HH];
__device__ float g_c0[BB * HH];
__device__ float g_c1[BB * HH];
__device__ float g_part[BB * G4];                  // layer1 partial gates
__device__ float g_rowloss[TS * BB];

__device__ __forceinline__ float sigmoidf_(float x) {
    return 1.0f / (1.0f + expf(-x));
}
__device__ __forceinline__ u64 fma2_(u64 a, u64 b, u64 c) {
    u64 d; asm("fma.rn.f32x2 %0, %1, %2, %3;" : "=l"(d) : "l"(a), "l"(b), "l"(c));
    return d;
}
__device__ __forceinline__ float2 unpack2_(u64 a) {
    float2 f; asm("mov.b64 {%0, %1}, %2;" : "=f"(f.x), "=f"(f.y) : "l"(a));
    return f;
}

// ---------------- init: zero recurrent state every replay --------------------
__global__ void init_state_kernel() {
    int i = blockIdx.x * blockDim.x + threadIdx.x;
    if (i < BB * HH) { g_h0buf[0][i] = 0.f; g_c0[i] = 0.f; g_c1[i] = 0.f; }
    if (i < BB * G4) g_part[i] = 0.f;
}

// ---------------- pre0 = gather(emb) @ w_ih0 + b0 ----------------------------
__global__ __launch_bounds__(256) void pre0_gemm_kernel(
    const int* __restrict__ sent, const float* __restrict__ wordvec,
    const float* __restrict__ w_ih0, const float* __restrict__ b0)
{
    __shared__ float As[4][64];
    __shared__ float Bs[4][64];
    const int t = blockIdx.y;
    const int colBase = blockIdx.x * 64;
    const int tid = threadIdx.x;
    const int tx = tid & 15, ty = tid >> 4;

    const float* arow = nullptr;
    if (tid < 64) {
        int token = sent[tid * TT + t];
        arow = wordvec + (size_t)token * EE;
    }
    const int bRow = tid >> 6, bCol = tid & 63;

    float acc[4][4] = {};
    for (int kt = 0; kt < 75; kt++) {
        __syncthreads();
        if (tid < 64) {
            float4 a = *(const float4*)(arow + kt * 4);
            As[0][tid] = a.x; As[1][tid] = a.y; As[2][tid] = a.z; As[3][tid] = a.w;
        }
        Bs[bRow][bCol] = w_ih0[(size_t)(kt * 4 + bRow) * G4 + colBase + bCol];
        __syncthreads();
#pragma unroll
        for (int k = 0; k < 4; k++) {
            float4 a4 = *(const float4*)&As[k][ty * 4];
            float4 b4 = *(const float4*)&Bs[k][tx * 4];
            acc[0][0] += a4.x * b4.x; acc[0][1] += a4.x * b4.y; acc[0][2] += a4.x * b4.z; acc[0][3] += a4.x * b4.w;
            acc[1][0] += a4.y * b4.x; acc[1][1] += a4.y * b4.y; acc[1][2] += a4.y * b4.z; acc[1][3] += a4.y * b4.w;
            acc[2][0] += a4.z * b4.x; acc[2][1] += a4.z * b4.y; acc[2][2] += a4.z * b4.z; acc[2][3] += a4.z * b4.w;
            acc[3][0] += a4.w * b4.x; acc[3][1] += a4.w * b4.y; acc[3][2] += a4.w * b4.z; acc[3][3] += a4.w * b4.w;
        }
    }
    float* dst = g_pre0 + ((size_t)t * 64) * G4 + colBase;
#pragma unroll
    for (int i = 0; i < 4; i++) {
        int b_ = ty * 4 + i;
#pragma unroll
        for (int j = 0; j < 4; j++) {
            int c = tx * 4 + j;
            dst[(size_t)b_ * G4 + c] = acc[i][j] + b0[colBase + c];
        }
    }
}

// ---------------- LSTM step GEMM (all modes K=1024) --------------------------
// phase 0: blocks [0,128) mode0 (layer0 full step), blocks [128,256) mode1
//          (layer1 partial: h1[t-1] @ w_hh1 -> g_part).
// phase 1: mode2 (layer1: h0[t] @ w_ih1 + g_part + b1 -> pointwise -> h1all[t]).
// CTA: BN = 8 j-cols x 4 gates, 256 threads. warp = one j, lanes = row pairs
// (l, l+32). h pre-duplicated in smem -> f32x2 operands with no dup-MOVs.
__global__ __launch_bounds__(256) void step_kernel(
    int t, int phase,
    const float* __restrict__ w_hh0, const float* __restrict__ w_ih1,
    const float* __restrict__ w_hh1, const float* __restrict__ b1)
{
    __shared__ __align__(16) float shs[2][32 * 132];  // h dup: [k][128(+pad)]
    __shared__ __align__(16) float wsm[2][32 * 36];   // w:     [k][8j x 4g(+pad)]

    const int tid = threadIdx.x;

    int mode;
    const float* W; const float* hin;
    if (phase == 0) {
        if (blockIdx.x < 128) { mode = 0; W = w_hh0; hin = g_h0buf[t & 1]; }
        else { mode = 1; W = w_hh1; hin = g_h1all + (size_t)(t - 1) * BB * HH; }
    } else { mode = 2; W = w_ih1; hin = g_h0buf[(t + 1) & 1]; }
    const int j0 = (blockIdx.x & 127) * 8;

    // ---- loader indices ----
    const int hb0 = tid >> 3;          // h row group 0..31 (rep adds 32)
    const int hc  = tid & 7;           // float4 chunk within 32-k tile
    const int wk  = tid >> 3;          // w k-row 0..31
    const int wr  = tid & 7;
    const int wg  = wr >> 1, wh = wr & 1;
    const float* wsrc = W + (size_t)wk * G4 + wg * HH + j0 + wh * 4;
    const int hposL = 2 * hb0;         // rows 0..31 slot
    const int hposH = 2 * hb0 + 64;    // rows 32..63 slot

    // ---- compute indices ----
    const int lane = tid & 31, warp = tid >> 5;
    const int hoffL = 2 * lane, hoffH = 2 * lane + 64, woff = warp * 4;

    // ---- store-tile helper ----
    auto sts_tile = [&](int buf, float4 ha, float4 hb, float4 wv) {
        float* s = shs[buf]; float* wd = wsm[buf];
        const int kb = hc * 4;
        *(float2*)&s[(kb + 0) * 132 + hposL] = make_float2(ha.x, ha.x);
        *(float2*)&s[(kb + 1) * 132 + hposL] = make_float2(ha.y, ha.y);
        *(float2*)&s[(kb + 2) * 132 + hposL] = make_float2(ha.z, ha.z);
        *(float2*)&s[(kb + 3) * 132 + hposL] = make_float2(ha.w, ha.w);
        *(float2*)&s[(kb + 0) * 132 + hposH] = make_float2(hb.x, hb.x);
        *(float2*)&s[(kb + 1) * 132 + hposH] = make_float2(hb.y, hb.y);
        *(float2*)&s[(kb + 2) * 132 + hposH] = make_float2(hb.z, hb.z);
        *(float2*)&s[(kb + 3) * 132 + hposH] = make_float2(hb.w, hb.w);
        wd[wk * 36 + (wh * 4 + 0) * 4 + wg] = wv.x;
        wd[wk * 36 + (wh * 4 + 1) * 4 + wg] = wv.y;
        wd[wk * 36 + (wh * 4 + 2) * 4 + wg] = wv.z;
        wd[wk * 36 + (wh * 4 + 3) * 4 + wg] = wv.w;
    };

    // ---- prologue: load tile 0 ----
    {
        float4 ha = *(const float4*)&hin[hb0 * HH + hc * 4];
        float4 hb = *(const float4*)&hin[(hb0 + 32) * HH + hc * 4];
        float4 wv = *(const float4*)&wsrc[0];
        sts_tile(0, ha, hb, wv);
    }

    u64 aLif = 0, aLgo = 0, aHif = 0, aHgo = 0;
    float4 nha, nhb, nwv;

    for (int tl = 0; tl < 32; tl++) {
        __syncthreads();
        const int cur = tl & 1;
        if (tl < 31) {
            const int kb = (tl + 1) * 32;
            nha = *(const float4*)&hin[hb0 * HH + kb + hc * 4];
            nhb = *(const float4*)&hin[(hb0 + 32) * HH + kb + hc * 4];
            nwv = *(const float4*)&wsrc[(size_t)kb * G4];
        }
        const float* s = shs[cur]; const float* wd = wsm[cur];
#pragma unroll
        for (int k = 0; k < 32; k++) {
            u64 hL = *(const u64*)&s[k * 132 + hoffL];
            u64 hH = *(const u64*)&s[k * 132 + hoffH];
            ulonglong2 wp = *(const ulonglong2*)&wd[k * 36 + woff];
            aLif = fma2_(hL, wp.x, aLif);
            aLgo = fma2_(hL, wp.y, aLgo);
            aHif = fma2_(hH, wp.x, aHif);
            aHgo = fma2_(hH, wp.y, aHgo);
        }
        if (tl < 31) sts_tile(cur ^ 1, nha, nhb, nwv);
    }

    // ---- epilogue ----
    const float2 LIF = unpack2_(aLif), LGO = unpack2_(aLgo);
    const float2 HIF = unpack2_(aHif), HGO = unpack2_(aHgo);
    const int j = j0 + warp;
    const int rL = lane, rH = lane + 32;

    if (mode == 1) {
        g_part[rL * G4 +          j] = LIF.x;
        g_part[rL * G4 + HH     + j] = LIF.y;
        g_part[rL * G4 + 2 * HH + j] = LGO.x;
        g_part[rL * G4 + 3 * HH + j] = LGO.y;
        g_part[rH * G4 +          j] = HIF.x;
        g_part[rH * G4 + HH     + j] = HIF.y;
        g_part[rH * G4 + 2 * HH + j] = HGO.x;
        g_part[rH * G4 + 3 * HH + j] = HGO.y;
        return;
    }

    float* cst; float* hout; const float* avb = nullptr;
    if (mode == 0) {
        cst = g_c0; hout = g_h0buf[(t + 1) & 1];
        avb = g_pre0 + (size_t)t * BB * G4;
    } else {
        cst = g_c1; hout = g_h1all + (size_t)t * BB * HH;
    }

#pragma unroll
    for (int half = 0; half < 2; half++) {
        const int r = half ? rH : rL;
        float gi = half ? HIF.x : LIF.x;
        float gf = half ? HIF.y : LIF.y;
        float gg = half ? HGO.x : LGO.x;
        float go = half ? HGO.y : LGO.y;
        if (mode == 0) {
            const float* av = avb + (size_t)r * G4;
            gi += av[j]; gf += av[HH + j]; gg += av[2 * HH + j]; go += av[3 * HH + j];
        } else {
            const float* pp = g_part + r * G4;
            gi += b1[j]          + pp[j];
            gf += b1[HH + j]     + pp[HH + j];
            gg += b1[2 * HH + j] + pp[2 * HH + j];
            go += b1[3 * HH + j] + pp[3 * HH + j];
        }
        float c  = cst[r * HH + j];
        float cn = sigmoidf_(gf) * c + sigmoidf_(gi) * tanhf(gg);
        float hn = sigmoidf_(go) * tanhf(cn);
        cst[r * HH + j]  = cn;
        hout[r * HH + j] = hn;
    }
}

// ---------------- logits = h1all @ w_out + b_out -----------------------------
__global__ __launch_bounds__(256) void logits_gemm_kernel(
    const float* __restrict__ w_out, const float* __restrict__ b_out,
    float* __restrict__ temp)
{
    __shared__ float As[16][64];
    __shared__ float Bs[16][64];
    const int t = blockIdx.y;
    const int colBase = blockIdx.x * 64;
    const int tid = threadIdx.x;
    const int tx = tid & 15, ty = tid >> 4;
    const int aRow = tid >> 2, aK = (tid & 3) * 4;
    const int bRow = tid >> 4, bCol = (tid & 15) * 4;
    const bool fullTile = (colBase + 64 <= VV);

    const float* Aptr = g_h1all + ((size_t)t * 64 + aRow) * HH + aK;

    float acc[4][4] = {};
    for (int kt = 0; kt < 64; kt++) {
        __syncthreads();
        float4 a = *(const float4*)(Aptr + kt * 16);
        As[aK + 0][aRow] = a.x; As[aK + 1][aRow] = a.y;
        As[aK + 2][aRow] = a.z; As[aK + 3][aRow] = a.w;
        int col = colBase + bCol;
        const float* bp = w_out + (size_t)(kt * 16 + bRow) * VV + col;
        if (fullTile || col + 3 < VV) {
            *(float4*)&Bs[bRow][bCol] = *(const float4*)bp;
        } else {
#pragma unroll
            for (int q = 0; q < 4; q++)
                Bs[bRow][bCol + q] = (col + q < VV) ? bp[q] : 0.f;
        }
        __syncthreads();
#pragma unroll
        for (int k = 0; k < 16; k++) {
            float4 a4 = *(const float4*)&As[k][ty * 4];
            float4 b4 = *(const float4*)&Bs[k][tx * 4];
            acc[0][0] += a4.x * b4.x; acc[0][1] += a4.x * b4.y; acc[0][2] += a4.x * b4.z; acc[0][3] += a4.x * b4.w;
            acc[1][0] += a4.y * b4.x; acc[1][1] += a4.y * b4.y; acc[1][2] += a4.y * b4.z; acc[1][3] += a4.y * b4.w;
            acc[2][0] += a4.z * b4.x; acc[2][1] += a4.z * b4.y; acc[2][2] += a4.z * b4.z; acc[2][3] += a4.z * b4.w;
            acc[3][0] += a4.w * b4.x; acc[3][1] += a4.w * b4.y; acc[3][2] += a4.w * b4.z; acc[3][3] += a4.w * b4.w;
        }
    }
#pragma unroll
    for (int i = 0; i < 4; i++) {
        int b_ = ty * 4 + i;
#pragma unroll
        for (int j = 0; j < 4; j++) {
            int col = colBase + tx * 4 + j;
            if (col < VV)
                temp[((size_t)b_ * TS + t) * VV + col] = acc[i][j] + b_out[col];
        }
    }
}

// ---------------- loss: per-row -logp/length (deterministic) -----------------
__global__ __launch_bounds__(256) void loss_row_kernel(
    const float* __restrict__ temp, const int* __restrict__ sent,
    const int* __restrict__ length)
{
    __shared__ float sm[256];
    __shared__ float ss[256];
    const int row = blockIdx.x;            // b*127 + t
    const int b = row / TS, t = row % TS;
    const float* x = temp + (size_t)row * VV;
    const int tid = threadIdx.x;

    float m = -1e30f, s = 0.f;
    for (int i = tid; i < VV; i += 256) {
        float v = x[i];
        float M = fmaxf(m, v);
        s = s * expf(m - M) + expf(v - M);
        m = M;
    }
    sm[tid] = m; ss[tid] = s;
    __syncthreads();
    for (int w = 128; w > 0; w >>= 1) {
        if (tid < w) {
            float m2 = sm[tid + w], s2 = ss[tid + w];
            float M = fmaxf(sm[tid], m2);
            ss[tid] = ss[tid] * expf(sm[tid] - M) + s2 * expf(m2 - M);
            sm[tid] = M;
        }
        __syncthreads();
    }
    if (tid == 0) {
        int gt = sent[b * TT + t + 1];
        float lse = sm[0] + logf(ss[0]);
        float res = 0.f;
        if (gt != 0) {
            float lp = x[gt] - lse;
            res = -lp / (float)length[b];
        }
        g_rowloss[row] = res;
    }
}

__global__ __launch_bounds__(256) void loss_final_kernel(float* __restrict__ out) {
    __shared__ float s[256];
    const int tid = threadIdx.x;
    float a = 0.f;
    for (int i = tid; i < TS * BB; i += 256) a += g_rowloss[i];
    s[tid] = a;
    __syncthreads();
    for (int w = 128; w > 0; w >>= 1) {
        if (tid < w) s[tid] += s[tid + w];
        __syncthreads();
    }
    if (tid == 0) out[0] = s[0];
}

// ---------------- host launcher ----------------------------------------------
extern "C" void kernel_launch(void* const* d_in, const int* in_sizes, int n_in,
                              void* d_out, int out_size)
{
    const int*   sent    = (const int*)d_in[0];
    const int*   length  = (const int*)d_in[1];
    const float* wordvec = (const float*)d_in[2];
    const float* w_ih0   = (const float*)d_in[3];
    const float* w_hh0   = (const float*)d_in[4];
    const float* b0      = (const float*)d_in[5];
    const float* w_ih1   = (const float*)d_in[6];
    const float* w_hh1   = (const float*)d_in[7];
    const float* b1      = (const float*)d_in[8];
    const float* w_out   = (const float*)d_in[9];
    const float* b_out   = (const float*)d_in[10];
    float* out = (float*)d_out;

    const long long TEMP_N = (long long)BB * TS * VV;
    int off = ((long long)out_size > TEMP_N) ? (int)((long long)out_size - TEMP_N) : 0;
    float* temp = out + off;

    init_state_kernel<<<1024, 256>>>();
    pre0_gemm_kernel<<<dim3(64, TS), 256>>>(sent, wordvec, w_ih0, b0);
    for (int t = 0; t < TS; t++) {
        step_kernel<<<(t == 0 ? 128 : 256), 256>>>(t, 0, w_hh0, w_ih1, w_hh1, b1);
        step_kernel<<<128, 256>>>(t, 1, w_hh0, w_ih1, w_hh1, b1);
    }
    logits_gemm_kernel<<<dim3(157, TS), 256>>>(w_out, b_out, temp);
    if (off > 0) {
        loss_row_kernel<<<TS * BB, 256>>>(temp, sent, length);
        loss_final_kernel<<<1, 256>>>(out);
    }
}